// round 11
// baseline (speedup 1.0000x reference)
#include <cuda_runtime.h>
#include <math.h>
#include <stdint.h>

#define BB 4
#define NN 50000
#define KK 128
#define NP (KK/2)                 // 64 gaussian pairs
#define GD 128
#define TPB 128
#define PPT 4
#define MPTS 512                  // points (rows) per CTA
#define NBLK 98                   // 98*512 = 50176 >= 50000
#define TOTAL_BLK (BB * NBLK)     // 392
#define NCHUNK 8                  // k-chunks of 16
#define KC 16
#define WSTRIDE 18                // W tile row stride (floats), also C staging stride
#define PSTRIDE 129               // P smem row stride

// Global scratch written by precompute kernel
__device__ float g_P[BB * 16 * KK];        // [b][col][k], cols: 0-8 Rrel, 9-11 u, 12 = 1
__device__ float g_argp[BB * NP * 12];     // per pair: ex(2) ey(2) ez(2) a(2) f(2) pad(2)

__device__ float        g_partial[TOTAL_BLK];
__device__ unsigned int g_count = 0;

__device__ __forceinline__ float ex2f(float x) {
    float y; asm("ex2.approx.ftz.f32 %0, %1;" : "=f"(y) : "f"(x)); return y;
}

union F2U { float2 f; unsigned long long u; };
__device__ __forceinline__ float2 fma2(float2 a, float2 b, float2 c) {
    F2U A, B, C, D; A.f = a; B.f = b; C.f = c;
    asm("fma.rn.f32x2 %0, %1, %2, %3;" : "=l"(D.u) : "l"(A.u), "l"(B.u), "l"(C.u));
    return D.f;
}

__device__ __forceinline__ void mma_tf32(float* c, uint32_t a0, uint32_t a1,
                                         uint32_t a2, uint32_t a3,
                                         uint32_t b0, uint32_t b1) {
    asm("mma.sync.aligned.m16n8k8.row.col.f32.tf32.tf32.f32 "
        "{%0,%1,%2,%3}, {%4,%5,%6,%7}, {%8,%9}, {%0,%1,%2,%3};"
        : "+f"(c[0]), "+f"(c[1]), "+f"(c[2]), "+f"(c[3])
        : "r"(a0), "r"(a1), "r"(a2), "r"(a3), "r"(b0), "r"(b1));
}

__device__ __forceinline__ float tf32r(float x) {
    float y; asm("cvt.rna.tf32.f32 %0, %1;" : "=f"(y) : "f"(x)); return y;
}

__global__ void precompute_kernel(const float* __restrict__ constants,
                                  const float* __restrict__ scales,
                                  const float* __restrict__ rot,
                                  const float* __restrict__ centers) {
    int idx = blockIdx.x * blockDim.x + threadIdx.x;
    if (idx >= BB * KK) return;
    int b = idx / KK;
    int k = idx - b * KK;
    int bt = (b + 1) & 3;

    const float* R  = rot + (size_t)(b  * KK + k) * 9;
    const float* Rt = rot + (size_t)(bt * KK + k) * 9;
    float Rr[9];
#pragma unroll
    for (int i = 0; i < 3; i++)
#pragma unroll
        for (int l = 0; l < 3; l++)
            Rr[i*3+l] = Rt[i*3+0]*R[l*3+0] + Rt[i*3+1]*R[l*3+1] + Rt[i*3+2]*R[l*3+2];
    const float* c  = centers + (size_t)(b  * KK + k) * 3;
    const float* ct = centers + (size_t)(bt * KK + k) * 3;
    float cx = c[0], cy = c[1], cz = c[2];
    float s  = scales[b * KK + k];
    float cc = constants[b * KK + k];
    float a  = -1.4426950408889634f / (2.0f * s * s);
    float lb = log2f(cc * cc);

    // P matrix [b][col][k]
    float* P = g_P + (size_t)b * 16 * KK;
#pragma unroll
    for (int j = 0; j < 9; j++) P[j * KK + k] = tf32r(Rr[j]);
    P[ 9 * KK + k] = tf32r(ct[0] - (Rr[0]*cx + Rr[1]*cy + Rr[2]*cz));
    P[10 * KK + k] = tf32r(ct[1] - (Rr[3]*cx + Rr[4]*cy + Rr[5]*cz));
    P[11 * KK + k] = tf32r(ct[2] - (Rr[6]*cx + Rr[7]*cy + Rr[8]*cz));
    P[12 * KK + k] = 1.0f;
    P[13 * KK + k] = 0.0f;
    P[14 * KK + k] = 0.0f;
    P[15 * KK + k] = 0.0f;

    // arg params (pair-interleaved)
    int pr = k >> 1, lane = k & 1;
    float* fp = g_argp + (size_t)(b * NP + pr) * 12;
    fp[0  + lane] = -2.0f * a * cx;
    fp[2  + lane] = -2.0f * a * cy;
    fp[4  + lane] = -2.0f * a * cz;
    fp[6  + lane] = a;
    fp[8  + lane] = a * (cx*cx + cy*cy + cz*cz) + lb;
    fp[10 + lane] = 0.0f;
}

__global__ __launch_bounds__(TPB, 3)
void fused_kernel(const float* __restrict__ samples,
                  const float* __restrict__ grid,
                  const float* __restrict__ w2g,
                  float* __restrict__ out) {
    int b   = blockIdx.x / NBLK;
    int blk = blockIdx.x - b * NBLK;
    int bt  = (b + 1) & 3;
    int base  = blk * MPTS;
    int limit = min(MPTS, NN - base);

    __shared__ float  Ws[MPTS * WSTRIDE];   // 36 KB: W tile, then C staging
    __shared__ float  Ps[16 * PSTRIDE];     // 8.25 KB
    __shared__ float4 argp[NP * 3];         // 3 KB
    __shared__ float  red[TPB];
    __shared__ bool   s_last;

    int tid  = threadIdx.x;
    int lane = tid & 31, warp = tid >> 5;
    int g    = lane >> 2, tg = lane & 3;

    // stage P and arg params
    {
        const float* Pg = g_P + (size_t)b * 16 * KK;
        for (int i = tid; i < 16 * KK; i += TPB) {
            int n = i >> 7, k = i & 127;
            Ps[n * PSTRIDE + k] = Pg[i];
        }
        const float4* ag = (const float4*)(g_argp + (size_t)b * NP * 12);
        for (int i = tid; i < NP * 3; i += TPB) argp[i] = ag[i];
    }

    // load points
    bool   ok[PPT];
    float2 px2[PPT], py2[PPT], pz2[PPT], sp2[PPT];
#pragma unroll
    for (int t = 0; t < PPT; t++) {
        int slot = tid + t * TPB;
        ok[t] = (slot < limit);
        float px = 0.f, py = 0.f, pz = 0.f;
        if (ok[t]) {
            const float* s6 = samples + (size_t)(b * NN + base + slot) * 6;
            px = s6[0]; py = s6[1]; pz = s6[2];
        }
        float sp = px*px + py*py + pz*pz;
        px2[t] = make_float2(px, px);
        py2[t] = make_float2(py, py);
        pz2[t] = make_float2(pz, pz);
        sp2[t] = make_float2(sp, sp);
    }
    __syncthreads();

    // accumulators: 8 m-tiles x 2 n-tiles x 4 regs
    float acc[8][2][4];
#pragma unroll
    for (int mt = 0; mt < 8; mt++)
#pragma unroll
        for (int nt = 0; nt < 2; nt++)
#pragma unroll
            for (int r = 0; r < 4; r++) acc[mt][nt][r] = 0.0f;

    for (int ch = 0; ch < NCHUNK; ch++) {
        // ---- phase 1: compute W chunk (cols = chunk-local k 0..15) ----
#pragma unroll
        for (int pp = 0; pp < 8; pp++) {
            int pr = ch * 8 + pp;
            float4 A0 = argp[pr*3+0];
            float4 A1 = argp[pr*3+1];
            float4 A2 = argp[pr*3+2];
            float2 ex = make_float2(A0.x, A0.y), ey = make_float2(A0.z, A0.w);
            float2 ez = make_float2(A1.x, A1.y), aa = make_float2(A1.z, A1.w);
            float2 ff = make_float2(A2.x, A2.y);
#pragma unroll
            for (int t = 0; t < PPT; t++) {
                float2 arg = fma2(aa, sp2[t],
                             fma2(ex, px2[t],
                             fma2(ey, py2[t],
                             fma2(ez, pz2[t], ff))));
                float2 w;
                w.x = ex2f(arg.x);
                w.y = ex2f(arg.y);
                int m = tid + t * TPB;
                *(float2*)&Ws[m * WSTRIDE + pp * 2] = w;
            }
        }
        __syncthreads();

        // ---- phase 2: mma over this chunk (k = 16 -> two k8 steps) ----
#pragma unroll
        for (int k8 = 0; k8 < 2; k8++) {
            int kg = ch * KC + k8 * 8 + tg;
            uint32_t b0[2], b1[2];
#pragma unroll
            for (int nt = 0; nt < 2; nt++) {
                b0[nt] = __float_as_uint(Ps[(nt*8 + g) * PSTRIDE + kg]);
                b1[nt] = __float_as_uint(Ps[(nt*8 + g) * PSTRIDE + kg + 4]);
            }
            int kc = k8 * 8 + tg;
#pragma unroll
            for (int mt = 0; mt < 8; mt++) {
                int row = warp * 128 + mt * 16 + g;
                uint32_t a0 = __float_as_uint(Ws[ row      * WSTRIDE + kc]);
                uint32_t a1 = __float_as_uint(Ws[(row + 8) * WSTRIDE + kc]);
                uint32_t a2 = __float_as_uint(Ws[ row      * WSTRIDE + kc + 4]);
                uint32_t a3 = __float_as_uint(Ws[(row + 8) * WSTRIDE + kc + 4]);
                mma_tf32(acc[mt][0], a0, a1, a2, a3, b0[0], b1[0]);
                mma_tf32(acc[mt][1], a0, a1, a2, a3, b0[1], b1[1]);
            }
        }
        __syncthreads();
    }

    // ---- stage C to smem (reuse Ws, stride WSTRIDE) ----
#pragma unroll
    for (int mt = 0; mt < 8; mt++)
#pragma unroll
        for (int nt = 0; nt < 2; nt++) {
            int row = warp * 128 + mt * 16 + g;
            int col = nt * 8 + tg * 2;
            *(float2*)&Ws[ row      * WSTRIDE + col] = make_float2(acc[mt][nt][0], acc[mt][nt][1]);
            *(float2*)&Ws[(row + 8) * WSTRIDE + col] = make_float2(acc[mt][nt][2], acc[mt][nt][3]);
        }
    __syncthreads();

    // ---- epilogue per point ----
    const float* M = w2g + bt * 16;
    const float* gg = grid + (size_t)bt * GD * GD * GD;
    const float dm = (float)(GD - 1);

    float val = 0.0f;
#pragma unroll
    for (int t = 0; t < PPT; t++) {
        if (!ok[t]) continue;
        const float* o = &Ws[(tid + t * TPB) * WSTRIDE];
        float px = px2[t].x, py = py2[t].x, pz = pz2[t].x;
        float inv = 1.0f / o[12];
        float bx = (o[0]*px + o[1]*py + o[2]*pz + o[ 9]) * inv;
        float by = (o[3]*px + o[4]*py + o[5]*pz + o[10]) * inv;
        float bz = (o[6]*px + o[7]*py + o[8]*pz + o[11]) * inv;

        float gx = M[0]*bx + M[1]*by + M[2]*bz  + M[3];
        float gy = M[4]*bx + M[5]*by + M[6]*bz  + M[7];
        float gz = M[8]*bx + M[9]*by + M[10]*bz + M[11];

        float nx = 2.0f * (gx / dm) - 1.0f;
        float ny = 2.0f * (gy / dm) - 1.0f;
        float nz = 2.0f * (gz / dm) - 1.0f;

        float x = fminf(fmaxf((nx + 1.0f) * 0.5f * dm, 0.0f), dm);
        float y = fminf(fmaxf((ny + 1.0f) * 0.5f * dm, 0.0f), dm);
        float z = fminf(fmaxf((nz + 1.0f) * 0.5f * dm, 0.0f), dm);

        float x0f = floorf(x), y0f = floorf(y), z0f = floorf(z);
        float fx = x - x0f, fy = y - y0f, fz = z - z0f;
        int x0 = (int)x0f, y0 = (int)y0f, z0 = (int)z0f;
        int x1 = min(x0 + 1, GD - 1);
        int y1 = min(y0 + 1, GD - 1);
        int z1 = min(z0 + 1, GD - 1);

        int zy00 = (z0 * GD + y0) * GD;
        int zy01 = (z0 * GD + y1) * GD;
        int zy10 = (z1 * GD + y0) * GD;
        int zy11 = (z1 * GD + y1) * GD;
        float c000 = __ldg(gg + zy00 + x0);
        float c001 = __ldg(gg + zy00 + x1);
        float c010 = __ldg(gg + zy01 + x0);
        float c011 = __ldg(gg + zy01 + x1);
        float c100 = __ldg(gg + zy10 + x0);
        float c101 = __ldg(gg + zy10 + x1);
        float c110 = __ldg(gg + zy11 + x0);
        float c111 = __ldg(gg + zy11 + x1);

        float c00 = c000 + (c001 - c000) * fx;
        float c01 = c010 + (c011 - c010) * fx;
        float c10 = c100 + (c101 - c100) * fx;
        float c11 = c110 + (c111 - c110) * fx;
        float c0  = c00 + (c01 - c00) * fy;
        float c1  = c10 + (c11 - c10) * fy;
        float sdf = c0 + (c1 - c0) * fz;
        val += sdf * sdf;
    }

    // ---- deterministic block reduction ----
    red[tid] = val;
    __syncthreads();
#pragma unroll
    for (int s = TPB / 2; s > 0; s >>= 1) {
        if (tid < s) red[tid] += red[tid + s];
        __syncthreads();
    }
    if (tid == 0) {
        g_partial[blockIdx.x] = red[0];
        __threadfence();
        unsigned int t = atomicAdd(&g_count, 1u);
        s_last = (t == TOTAL_BLK - 1);
    }
    __syncthreads();

    if (s_last) {
        float s = 0.0f;
        for (int i = tid; i < TOTAL_BLK; i += TPB) s += g_partial[i];
        red[tid] = s;
        __syncthreads();
#pragma unroll
        for (int st = TPB / 2; st > 0; st >>= 1) {
            if (tid < st) red[tid] += red[tid + st];
            __syncthreads();
        }
        if (tid == 0) {
            out[0] = red[0] * (1.0f / (float)NN);
            g_count = 0;
        }
    }
}

extern "C" void kernel_launch(void* const* d_in, const int* in_sizes, int n_in,
                              void* d_out, int out_size) {
    const float* constants = (const float*)d_in[0];   // (B,K)
    const float* scales    = (const float*)d_in[1];   // (B,K)
    const float* rotations = (const float*)d_in[2];   // (B,K,3,3)
    const float* centers   = (const float*)d_in[3];   // (B,K,3)
    const float* samples   = (const float*)d_in[4];   // (B,N,6)
    const float* grid      = (const float*)d_in[5];   // (B,GD,GD,GD)
    const float* w2g       = (const float*)d_in[6];   // (B,4,4)
    float* out = (float*)d_out;

    precompute_kernel<<<2, 256>>>(constants, scales, rotations, centers);
    fused_kernel<<<TOTAL_BLK, TPB>>>(samples, grid, w2g, out);
}

// round 13
// speedup vs baseline: 1.6423x; 1.6423x over previous
#include <cuda_runtime.h>
#include <math.h>
#include <stdint.h>

#define BB 4
#define NN 50000
#define KK 128
#define GD 128
#define TPB 256
#define PPC 256                    // points per CTA (8 warps x 2 mtiles x 16)
#define NBLK 196                   // 196*256 = 50176 >= 50000
#define TOTAL_BLK (BB * NBLK)      // 784

// Precomputed data:
// g_P2: B-operand (tf32), packed float2 over (k, k+4):
//   [b][n(16)][k8(16)][jj(4)] float2 { P[n][8*k8+jj], P[n][8*k8+jj+4] }
//   n: 0-8 = Rrel (row-major), 9-11 = u (= ct - Rrel*c), 12 = 1, 13-15 = 0
// g_A2: exp-arg params, same (k,k+4) float2 packing:
//   [b][k8(16)][par(5)][jj(4)] float2 ; par: 0=ex 1=ey 2=ez 3=a 4=f
__device__ float2 g_P2[BB * 16 * 16 * 4];
__device__ float2 g_A2[BB * 16 * 5 * 4];

__device__ float        g_partial[TOTAL_BLK];
__device__ unsigned int g_count = 0;

__device__ __forceinline__ float ex2f(float x) {
    float y; asm("ex2.approx.ftz.f32 %0, %1;" : "=f"(y) : "f"(x)); return y;
}
__device__ __forceinline__ float tf32r(float x) {
    float y; asm("cvt.rna.tf32.f32 %0, %1;" : "=f"(y) : "f"(x)); return y;
}

union F2U { float2 f; unsigned long long u; };
__device__ __forceinline__ float2 fma2(float2 a, float2 b, float2 c) {
    F2U A, B, C, D; A.f = a; B.f = b; C.f = c;
    asm("fma.rn.f32x2 %0, %1, %2, %3;" : "=l"(D.u) : "l"(A.u), "l"(B.u), "l"(C.u));
    return D.f;
}

__device__ __forceinline__ void mma_tf32(float* c, float a0, float a1,
                                         float a2, float a3,
                                         float b0, float b1) {
    asm("mma.sync.aligned.m16n8k8.row.col.f32.tf32.tf32.f32 "
        "{%0,%1,%2,%3}, {%4,%5,%6,%7}, {%8,%9}, {%0,%1,%2,%3};"
        : "+f"(c[0]), "+f"(c[1]), "+f"(c[2]), "+f"(c[3])
        : "r"(__float_as_uint(a0)), "r"(__float_as_uint(a1)),
          "r"(__float_as_uint(a2)), "r"(__float_as_uint(a3)),
          "r"(__float_as_uint(b0)), "r"(__float_as_uint(b1)));
}

__global__ void precompute_kernel(const float* __restrict__ constants,
                                  const float* __restrict__ scales,
                                  const float* __restrict__ rot,
                                  const float* __restrict__ centers) {
    int idx = blockIdx.x * blockDim.x + threadIdx.x;
    if (idx >= BB * KK) return;
    int b = idx / KK;
    int k = idx - b * KK;
    int bt = (b + 1) & 3;

    const float* R  = rot + (size_t)(b  * KK + k) * 9;
    const float* Rt = rot + (size_t)(bt * KK + k) * 9;
    float Rr[9];
#pragma unroll
    for (int i = 0; i < 3; i++)
#pragma unroll
        for (int l = 0; l < 3; l++)
            Rr[i*3+l] = Rt[i*3+0]*R[l*3+0] + Rt[i*3+1]*R[l*3+1] + Rt[i*3+2]*R[l*3+2];
    const float* c  = centers + (size_t)(b  * KK + k) * 3;
    const float* ct = centers + (size_t)(bt * KK + k) * 3;
    float cx = c[0], cy = c[1], cz = c[2];
    float s  = scales[b * KK + k];
    float cc = constants[b * KK + k];
    float a  = -1.4426950408889634f / (2.0f * s * s);
    float lb = log2f(cc * cc);

    int k8 = k >> 3, j = k & 7, jj = j & 3, half = j >> 2;

    // P columns
    float v[16];
#pragma unroll
    for (int n = 0; n < 9; n++) v[n] = tf32r(Rr[n]);
    v[ 9] = tf32r(ct[0] - (Rr[0]*cx + Rr[1]*cy + Rr[2]*cz));
    v[10] = tf32r(ct[1] - (Rr[3]*cx + Rr[4]*cy + Rr[5]*cz));
    v[11] = tf32r(ct[2] - (Rr[6]*cx + Rr[7]*cy + Rr[8]*cz));
    v[12] = 1.0f; v[13] = 0.0f; v[14] = 0.0f; v[15] = 0.0f;

    float* P2 = (float*)g_P2;
#pragma unroll
    for (int n = 0; n < 16; n++)
        P2[((((b*16 + n)*16 + k8)*4 + jj) << 1) + half] = v[n];

    float pv[5];
    pv[0] = -2.0f * a * cx;
    pv[1] = -2.0f * a * cy;
    pv[2] = -2.0f * a * cz;
    pv[3] = a;
    pv[4] = a * (cx*cx + cy*cy + cz*cz) + lb;
    float* A2 = (float*)g_A2;
#pragma unroll
    for (int par = 0; par < 5; par++)
        A2[((((b*16 + k8)*5 + par)*4 + jj) << 1) + half] = pv[par];
}

#define PN_STRIDE 65      // float2 stride per n row in sP (16*4 + 1 pad)

__global__ __launch_bounds__(TPB, 3)
void fused_kernel(const float* __restrict__ samples,
                  const float* __restrict__ grid,
                  const float* __restrict__ w2g,
                  float* __restrict__ out) {
    int b   = blockIdx.x / NBLK;
    int blk = blockIdx.x - b * NBLK;
    int bt  = (b + 1) & 3;
    int base = blk * PPC;

    __shared__ float2 sP[16 * PN_STRIDE];    // 8.3 KB  [n][k8*4+jj] padded
    __shared__ float2 sA[16 * 5 * 4];        // 2.5 KB
    __shared__ float  pxs[PPC], pys[PPC], pzs[PPC], sps[PPC];
    __shared__ float  Cst[PPC * 17];         // 17.4 KB
    __shared__ float  red[TPB];
    __shared__ bool   s_last;

    int tid  = threadIdx.x;
    int lane = tid & 31, warp = tid >> 5;
    int g    = lane >> 2, tg = lane & 3;
    int wbase = warp * 32;

    // ---- stage params + points ----
    {
        const float2* Pg = g_P2 + (size_t)b * 16 * 16 * 4;
        for (int i = tid; i < 16 * 16 * 4; i += TPB) {
            int n = i >> 6, r = i & 63;
            sP[n * PN_STRIDE + r] = Pg[i];
        }
        const float2* Ag = g_A2 + (size_t)b * 16 * 5 * 4;
        for (int i = tid; i < 16 * 5 * 4; i += TPB) sA[i] = Ag[i];

        int gi = base + tid;
        float px = 0.f, py = 0.f, pz = 0.f;
        if (gi < NN) {
            const float* s6 = samples + (size_t)(b * NN + gi) * 6;
            px = s6[0]; py = s6[1]; pz = s6[2];
        }
        pxs[tid] = px; pys[tid] = py; pzs[tid] = pz;
        sps[tid] = px*px + py*py + pz*pz;
    }
    __syncthreads();

    // per-thread point coords for its fragment rows: [mt][r] rows = wbase + mt*16 + g + 8r
    float2 pxc[2][2], pyc[2][2], pzc[2][2], spc[2][2];
#pragma unroll
    for (int mt = 0; mt < 2; mt++)
#pragma unroll
        for (int r = 0; r < 2; r++) {
            int m = wbase + mt * 16 + g + 8 * r;
            float vx = pxs[m], vy = pys[m], vz = pzs[m], vs = sps[m];
            pxc[mt][r] = make_float2(vx, vx);
            pyc[mt][r] = make_float2(vy, vy);
            pzc[mt][r] = make_float2(vz, vz);
            spc[mt][r] = make_float2(vs, vs);
        }

    float acc[2][2][4];
#pragma unroll
    for (int mt = 0; mt < 2; mt++)
#pragma unroll
        for (int nt = 0; nt < 2; nt++)
#pragma unroll
            for (int q = 0; q < 4; q++) acc[mt][nt][q] = 0.0f;

#pragma unroll 4
    for (int k8 = 0; k8 < 16; k8++) {
        const float2* ap = sA + k8 * 20;
        float2 ex = ap[0*4 + tg];
        float2 ey = ap[1*4 + tg];
        float2 ez = ap[2*4 + tg];
        float2 aa = ap[3*4 + tg];
        float2 ff = ap[4*4 + tg];
        float2 b0 = sP[ g      * PN_STRIDE + k8*4 + tg];   // n = g
        float2 b1 = sP[(g + 8) * PN_STRIDE + k8*4 + tg];   // n = g + 8

#pragma unroll
        for (int mt = 0; mt < 2; mt++) {
            float2 w0, w1;
            {
                float2 arg = fma2(aa, spc[mt][0],
                             fma2(ex, pxc[mt][0],
                             fma2(ey, pyc[mt][0],
                             fma2(ez, pzc[mt][0], ff))));
                w0.x = ex2f(arg.x); w0.y = ex2f(arg.y);
            }
            {
                float2 arg = fma2(aa, spc[mt][1],
                             fma2(ex, pxc[mt][1],
                             fma2(ey, pyc[mt][1],
                             fma2(ez, pzc[mt][1], ff))));
                w1.x = ex2f(arg.x); w1.y = ex2f(arg.y);
            }
            // a0=A[g][tg]  a1=A[g+8][tg]  a2=A[g][tg+4]  a3=A[g+8][tg+4]
            mma_tf32(acc[mt][0], w0.x, w1.x, w0.y, w1.y, b0.x, b0.y);
            mma_tf32(acc[mt][1], w0.x, w1.x, w0.y, w1.y, b1.x, b1.y);
        }
    }

    // ---- stage C (rows = points, cols 0..15, stride 17) ----
#pragma unroll
    for (int mt = 0; mt < 2; mt++) {
        int row = wbase + mt * 16 + g;
#pragma unroll
        for (int nt = 0; nt < 2; nt++) {
            int col = nt * 8 + tg * 2;
            Cst[ row      * 17 + col    ] = acc[mt][nt][0];
            Cst[ row      * 17 + col + 1] = acc[mt][nt][1];
            Cst[(row + 8) * 17 + col    ] = acc[mt][nt][2];
            Cst[(row + 8) * 17 + col + 1] = acc[mt][nt][3];
        }
    }
    __syncthreads();

    // ---- epilogue: one point per thread ----
    const float* M  = w2g + bt * 16;
    const float* gg = grid + (size_t)bt * GD * GD * GD;
    const float dm  = (float)(GD - 1);

    float val = 0.0f;
    if (base + tid < NN) {
        const float* o = &Cst[tid * 17];
        float px = pxs[tid], py = pys[tid], pz = pzs[tid];
        float inv = 1.0f / o[12];
        float bx = (o[0]*px + o[1]*py + o[2]*pz + o[ 9]) * inv;
        float by = (o[3]*px + o[4]*py + o[5]*pz + o[10]) * inv;
        float bz = (o[6]*px + o[7]*py + o[8]*pz + o[11]) * inv;

        float gx = M[0]*bx + M[1]*by + M[2]*bz  + M[3];
        float gy = M[4]*bx + M[5]*by + M[6]*bz  + M[7];
        float gz = M[8]*bx + M[9]*by + M[10]*bz + M[11];

        float nx = 2.0f * (gx / dm) - 1.0f;
        float ny = 2.0f * (gy / dm) - 1.0f;
        float nz = 2.0f * (gz / dm) - 1.0f;

        float x = fminf(fmaxf((nx + 1.0f) * 0.5f * dm, 0.0f), dm);
        float y = fminf(fmaxf((ny + 1.0f) * 0.5f * dm, 0.0f), dm);
        float z = fminf(fmaxf((nz + 1.0f) * 0.5f * dm, 0.0f), dm);

        float x0f = floorf(x), y0f = floorf(y), z0f = floorf(z);
        float fx = x - x0f, fy = y - y0f, fz = z - z0f;
        int x0 = (int)x0f, y0 = (int)y0f, z0 = (int)z0f;
        int x1 = min(x0 + 1, GD - 1);
        int y1 = min(y0 + 1, GD - 1);
        int z1 = min(z0 + 1, GD - 1);

        int zy00 = (z0 * GD + y0) * GD;
        int zy01 = (z0 * GD + y1) * GD;
        int zy10 = (z1 * GD + y0) * GD;
        int zy11 = (z1 * GD + y1) * GD;
        float c000 = __ldg(gg + zy00 + x0);
        float c001 = __ldg(gg + zy00 + x1);
        float c010 = __ldg(gg + zy01 + x0);
        float c011 = __ldg(gg + zy01 + x1);
        float c100 = __ldg(gg + zy10 + x0);
        float c101 = __ldg(gg + zy10 + x1);
        float c110 = __ldg(gg + zy11 + x0);
        float c111 = __ldg(gg + zy11 + x1);

        float c00 = c000 + (c001 - c000) * fx;
        float c01 = c010 + (c011 - c010) * fx;
        float c10 = c100 + (c101 - c100) * fx;
        float c11 = c110 + (c111 - c110) * fx;
        float c0  = c00 + (c01 - c00) * fy;
        float c1  = c10 + (c11 - c10) * fy;
        float sdf = c0 + (c1 - c0) * fz;
        val = sdf * sdf;
    }

    // ---- deterministic block reduction ----
    red[tid] = val;
    __syncthreads();
#pragma unroll
    for (int s = TPB / 2; s > 0; s >>= 1) {
        if (tid < s) red[tid] += red[tid + s];
        __syncthreads();
    }
    if (tid == 0) {
        g_partial[blockIdx.x] = red[0];
        __threadfence();
        unsigned int t = atomicAdd(&g_count, 1u);
        s_last = (t == TOTAL_BLK - 1);
    }
    __syncthreads();

    if (s_last) {
        float s = 0.0f;
        for (int i = tid; i < TOTAL_BLK; i += TPB) s += g_partial[i];
        red[tid] = s;
        __syncthreads();
#pragma unroll
        for (int st = TPB / 2; st > 0; st >>= 1) {
            if (tid < st) red[tid] += red[tid + st];
            __syncthreads();
        }
        if (tid == 0) {
            out[0] = red[0] * (1.0f / (float)NN);
            g_count = 0;
        }
    }
}

extern "C" void kernel_launch(void* const* d_in, const int* in_sizes, int n_in,
                              void* d_out, int out_size) {
    const float* constants = (const float*)d_in[0];   // (B,K)
    const float* scales    = (const float*)d_in[1];   // (B,K)
    const float* rotations = (const float*)d_in[2];   // (B,K,3,3)
    const float* centers   = (const float*)d_in[3];   // (B,K,3)
    const float* samples   = (const float*)d_in[4];   // (B,N,6)
    const float* grid      = (const float*)d_in[5];   // (B,GD,GD,GD)
    const float* w2g       = (const float*)d_in[6];   // (B,4,4)
    float* out = (float*)d_out;

    precompute_kernel<<<2, 256>>>(constants, scales, rotations, centers);
    fused_kernel<<<TOTAL_BLK, TPB>>>(samples, grid, w2g, out);
}

// round 14
// speedup vs baseline: 1.7739x; 1.0801x over previous
#include <cuda_runtime.h>
#include <math.h>
#include <stdint.h>

#define BB 4
#define NN 50000
#define KK 128
#define GD 128
#define TPB 128
#define PPC 256                    // points per CTA: 4 warps x 4 mtiles x 16
#define NBLK 196                   // 196*256 = 50176 >= 50000
#define TOTAL_BLK (BB * NBLK)      // 784
#define MT 4                       // m-tiles per warp

// g_P4: B operand, float4 {P[n=g][k], P[n=g][k+4], P[n=g+8][k], P[n=g+8][k+4]}
//   laid out [b][k8(16)][g(8)][tg(4)]  (k = k8*8 + tg)
//   n: 0-8 = Rrel row-major, 9-11 = u (= ct - Rrel*c), 12 = 1, 13-15 = 0
// g_A4: exp-arg params [b][k8(16)][j(3)][tg(4)] float4:
//   j0 = {ex_k, ex_k+4, ey_k, ey_k+4}, j1 = {ez_k, ez_k+4, a_k, a_k+4}, j2 = {f_k, f_k+4, 0, 0}
__device__ float4 g_P4[BB * 16 * 8 * 4];
__device__ float4 g_A4[BB * 16 * 3 * 4];

__device__ float        g_partial[TOTAL_BLK];
__device__ unsigned int g_count = 0;

__device__ __forceinline__ float ex2f(float x) {
    float y; asm("ex2.approx.ftz.f32 %0, %1;" : "=f"(y) : "f"(x)); return y;
}
__device__ __forceinline__ float tf32r(float x) {
    float y; asm("cvt.rna.tf32.f32 %0, %1;" : "=f"(y) : "f"(x)); return y;
}

__device__ __forceinline__ void mma_tf32(float* c, float a0, float a1,
                                         float a2, float a3,
                                         float b0, float b1) {
    asm("mma.sync.aligned.m16n8k8.row.col.f32.tf32.tf32.f32 "
        "{%0,%1,%2,%3}, {%4,%5,%6,%7}, {%8,%9}, {%0,%1,%2,%3};"
        : "+f"(c[0]), "+f"(c[1]), "+f"(c[2]), "+f"(c[3])
        : "r"(__float_as_uint(a0)), "r"(__float_as_uint(a1)),
          "r"(__float_as_uint(a2)), "r"(__float_as_uint(a3)),
          "r"(__float_as_uint(b0)), "r"(__float_as_uint(b1)));
}

__global__ void precompute_kernel(const float* __restrict__ constants,
                                  const float* __restrict__ scales,
                                  const float* __restrict__ rot,
                                  const float* __restrict__ centers) {
    int idx = blockIdx.x * blockDim.x + threadIdx.x;
    if (idx >= BB * KK) return;
    int b = idx / KK;
    int k = idx - b * KK;
    int bt = (b + 1) & 3;

    const float* R  = rot + (size_t)(b  * KK + k) * 9;
    const float* Rt = rot + (size_t)(bt * KK + k) * 9;
    float Rr[9];
#pragma unroll
    for (int i = 0; i < 3; i++)
#pragma unroll
        for (int l = 0; l < 3; l++)
            Rr[i*3+l] = Rt[i*3+0]*R[l*3+0] + Rt[i*3+1]*R[l*3+1] + Rt[i*3+2]*R[l*3+2];
    const float* c  = centers + (size_t)(b  * KK + k) * 3;
    const float* ct = centers + (size_t)(bt * KK + k) * 3;
    float cx = c[0], cy = c[1], cz = c[2];
    float s  = scales[b * KK + k];
    float cc = constants[b * KK + k];
    float a  = -1.4426950408889634f / (2.0f * s * s);
    float lb = log2f(cc * cc);

    int k8 = k >> 3, j = k & 7, tg = j & 3, half = j >> 2;

    float v[16];
#pragma unroll
    for (int n = 0; n < 9; n++) v[n] = tf32r(Rr[n]);
    v[ 9] = tf32r(ct[0] - (Rr[0]*cx + Rr[1]*cy + Rr[2]*cz));
    v[10] = tf32r(ct[1] - (Rr[3]*cx + Rr[4]*cy + Rr[5]*cz));
    v[11] = tf32r(ct[2] - (Rr[6]*cx + Rr[7]*cy + Rr[8]*cz));
    v[12] = 1.0f; v[13] = 0.0f; v[14] = 0.0f; v[15] = 0.0f;

    float* P4 = (float*)g_P4;
#pragma unroll
    for (int n = 0; n < 16; n++) {
        int g8 = n & 7, hi = n >> 3;
        P4[((((b*16 + k8)*8 + g8)*4 + tg) << 2) + hi*2 + half] = v[n];
    }

    float* A4 = (float*)g_A4;
    float ex = -2.0f * a * cx;
    float ey = -2.0f * a * cy;
    float ez = -2.0f * a * cz;
    float ff = a * (cx*cx + cy*cy + cz*cz) + lb;
    int abase = ((b*16 + k8)*3) * 16 + tg * 4;
    A4[abase +  0 + half]     = ex;
    A4[abase +  0 + 2 + half] = ey;
    A4[abase + 16 + half]     = ez;
    A4[abase + 16 + 2 + half] = a;
    A4[abase + 32 + half]     = ff;
    // comps 2,3 of j2 stay zero-initialized
}

__global__ __launch_bounds__(TPB, 5)
void fused_kernel(const float* __restrict__ samples,
                  const float* __restrict__ grid,
                  const float* __restrict__ w2g,
                  float* __restrict__ out) {
    int b   = blockIdx.x / NBLK;
    int blk = blockIdx.x - b * NBLK;
    int bt  = (b + 1) & 3;
    int base = blk * PPC;

    __shared__ float4 sP4[16 * 8 * 4];      // 8 KB
    __shared__ float4 sA4[16 * 3 * 4];      // 3 KB
    __shared__ float  pxs[PPC], pys[PPC], pzs[PPC], sps[PPC];  // 4 KB
    __shared__ float  Cst[PPC * 17];        // 17.4 KB
    __shared__ float  red[TPB];
    __shared__ bool   s_last;

    int tid  = threadIdx.x;
    int lane = tid & 31, warp = tid >> 5;
    int g    = lane >> 2, tg = lane & 3;
    int wbase = warp * 64;

    // ---- stage params + points ----
    {
        const float4* Pg = g_P4 + (size_t)b * 512;
        for (int i = tid; i < 512; i += TPB) sP4[i] = Pg[i];
        const float4* Ag = g_A4 + (size_t)b * 192;
        for (int i = tid; i < 192; i += TPB) sA4[i] = Ag[i];

#pragma unroll
        for (int t = 0; t < 2; t++) {
            int slot = tid + t * TPB;
            int gi = base + slot;
            float px = 0.f, py = 0.f, pz = 0.f;
            if (gi < NN) {
                const float* s6 = samples + (size_t)(b * NN + gi) * 6;
                px = s6[0]; py = s6[1]; pz = s6[2];
            }
            pxs[slot] = px; pys[slot] = py; pzs[slot] = pz;
            sps[slot] = px*px + py*py + pz*pz;
        }
    }
    __syncthreads();

    // per-thread fragment-row coords (scalar): rows = wbase + mt*16 + g + 8r
    float cxr[MT][2], cyr[MT][2], czr[MT][2], csr[MT][2];
#pragma unroll
    for (int mt = 0; mt < MT; mt++)
#pragma unroll
        for (int r = 0; r < 2; r++) {
            int m = wbase + mt * 16 + g + 8 * r;
            cxr[mt][r] = pxs[m]; cyr[mt][r] = pys[m];
            czr[mt][r] = pzs[m]; csr[mt][r] = sps[m];
        }

    float acc[MT][2][4];
#pragma unroll
    for (int mt = 0; mt < MT; mt++)
#pragma unroll
        for (int nt = 0; nt < 2; nt++)
#pragma unroll
            for (int q = 0; q < 4; q++) acc[mt][nt][q] = 0.0f;

#pragma unroll 2
    for (int k8 = 0; k8 < 16; k8++) {
        float4 pb = sP4[k8*32 + g*4 + tg];          // conflict-free LDS.128
        float4 A0 = sA4[k8*12 + 0 + tg];
        float4 A1 = sA4[k8*12 + 4 + tg];
        float4 A2 = sA4[k8*12 + 8 + tg];
        // A0 = {ex_l, ex_h, ey_l, ey_h}; A1 = {ez_l, ez_h, a_l, a_h}; A2 = {f_l, f_h, -, -}

#pragma unroll
        for (int mt = 0; mt < MT; mt++) {
            float al0 = fmaf(A1.z, csr[mt][0], fmaf(A0.x, cxr[mt][0],
                        fmaf(A0.z, cyr[mt][0], fmaf(A1.x, czr[mt][0], A2.x))));
            float ah0 = fmaf(A1.w, csr[mt][0], fmaf(A0.y, cxr[mt][0],
                        fmaf(A0.w, cyr[mt][0], fmaf(A1.y, czr[mt][0], A2.y))));
            float al1 = fmaf(A1.z, csr[mt][1], fmaf(A0.x, cxr[mt][1],
                        fmaf(A0.z, cyr[mt][1], fmaf(A1.x, czr[mt][1], A2.x))));
            float ah1 = fmaf(A1.w, csr[mt][1], fmaf(A0.y, cxr[mt][1],
                        fmaf(A0.w, cyr[mt][1], fmaf(A1.y, czr[mt][1], A2.y))));
            float w00 = ex2f(al0);   // A[row g   ][k=tg]
            float w10 = ex2f(al1);   // A[row g+8 ][k=tg]
            float w01 = ex2f(ah0);   // A[row g   ][k=tg+4]
            float w11 = ex2f(ah1);   // A[row g+8 ][k=tg+4]
            mma_tf32(acc[mt][0], w00, w10, w01, w11, pb.x, pb.y);
            mma_tf32(acc[mt][1], w00, w10, w01, w11, pb.z, pb.w);
        }
    }

    // ---- stage C (rows = points, cols 0..15, stride 17) ----
#pragma unroll
    for (int mt = 0; mt < MT; mt++) {
        int row = wbase + mt * 16 + g;
#pragma unroll
        for (int nt = 0; nt < 2; nt++) {
            int col = nt * 8 + tg * 2;
            Cst[ row      * 17 + col    ] = acc[mt][nt][0];
            Cst[ row      * 17 + col + 1] = acc[mt][nt][1];
            Cst[(row + 8) * 17 + col    ] = acc[mt][nt][2];
            Cst[(row + 8) * 17 + col + 1] = acc[mt][nt][3];
        }
    }
    __syncthreads();

    // ---- epilogue: 2 points per thread ----
    const float* M  = w2g + bt * 16;
    const float* gg = grid + (size_t)bt * GD * GD * GD;
    const float dm  = (float)(GD - 1);

    float val = 0.0f;
#pragma unroll
    for (int t = 0; t < 2; t++) {
        int slot = tid + t * TPB;
        if (base + slot >= NN) continue;
        const float* o = &Cst[slot * 17];
        float px = pxs[slot], py = pys[slot], pz = pzs[slot];
        float inv = 1.0f / o[12];
        float bx = (o[0]*px + o[1]*py + o[2]*pz + o[ 9]) * inv;
        float by = (o[3]*px + o[4]*py + o[5]*pz + o[10]) * inv;
        float bz = (o[6]*px + o[7]*py + o[8]*pz + o[11]) * inv;

        float gx = M[0]*bx + M[1]*by + M[2]*bz  + M[3];
        float gy = M[4]*bx + M[5]*by + M[6]*bz  + M[7];
        float gz = M[8]*bx + M[9]*by + M[10]*bz + M[11];

        float nx = 2.0f * (gx / dm) - 1.0f;
        float ny = 2.0f * (gy / dm) - 1.0f;
        float nz = 2.0f * (gz / dm) - 1.0f;

        float x = fminf(fmaxf((nx + 1.0f) * 0.5f * dm, 0.0f), dm);
        float y = fminf(fmaxf((ny + 1.0f) * 0.5f * dm, 0.0f), dm);
        float z = fminf(fmaxf((nz + 1.0f) * 0.5f * dm, 0.0f), dm);

        float x0f = floorf(x), y0f = floorf(y), z0f = floorf(z);
        float fx = x - x0f, fy = y - y0f, fz = z - z0f;
        int x0 = (int)x0f, y0 = (int)y0f, z0 = (int)z0f;
        int x1 = min(x0 + 1, GD - 1);
        int y1 = min(y0 + 1, GD - 1);
        int z1 = min(z0 + 1, GD - 1);

        int zy00 = (z0 * GD + y0) * GD;
        int zy01 = (z0 * GD + y1) * GD;
        int zy10 = (z1 * GD + y0) * GD;
        int zy11 = (z1 * GD + y1) * GD;
        float c000 = __ldg(gg + zy00 + x0);
        float c001 = __ldg(gg + zy00 + x1);
        float c010 = __ldg(gg + zy01 + x0);
        float c011 = __ldg(gg + zy01 + x1);
        float c100 = __ldg(gg + zy10 + x0);
        float c101 = __ldg(gg + zy10 + x1);
        float c110 = __ldg(gg + zy11 + x0);
        float c111 = __ldg(gg + zy11 + x1);

        float c00 = c000 + (c001 - c000) * fx;
        float c01 = c010 + (c011 - c010) * fx;
        float c10 = c100 + (c101 - c100) * fx;
        float c11 = c110 + (c111 - c110) * fx;
        float c0  = c00 + (c01 - c00) * fy;
        float c1  = c10 + (c11 - c10) * fy;
        float sdf = c0 + (c1 - c0) * fz;
        val += sdf * sdf;
    }

    // ---- deterministic block reduction ----
    red[tid] = val;
    __syncthreads();
#pragma unroll
    for (int s = TPB / 2; s > 0; s >>= 1) {
        if (tid < s) red[tid] += red[tid + s];
        __syncthreads();
    }
    if (tid == 0) {
        g_partial[blockIdx.x] = red[0];
        __threadfence();
        unsigned int t = atomicAdd(&g_count, 1u);
        s_last = (t == TOTAL_BLK - 1);
    }
    __syncthreads();

    if (s_last) {
        float s = 0.0f;
        for (int i = tid; i < TOTAL_BLK; i += TPB) s += g_partial[i];
        red[tid] = s;
        __syncthreads();
#pragma unroll
        for (int st = TPB / 2; st > 0; st >>= 1) {
            if (tid < st) red[tid] += red[tid + st];
            __syncthreads();
        }
        if (tid == 0) {
            out[0] = red[0] * (1.0f / (float)NN);
            g_count = 0;
        }
    }
}

extern "C" void kernel_launch(void* const* d_in, const int* in_sizes, int n_in,
                              void* d_out, int out_size) {
    const float* constants = (const float*)d_in[0];   // (B,K)
    const float* scales    = (const float*)d_in[1];   // (B,K)
    const float* rotations = (const float*)d_in[2];   // (B,K,3,3)
    const float* centers   = (const float*)d_in[3];   // (B,K,3)
    const float* samples   = (const float*)d_in[4];   // (B,N,6)
    const float* grid      = (const float*)d_in[5];   // (B,GD,GD,GD)
    const float* w2g       = (const float*)d_in[6];   // (B,4,4)
    float* out = (float*)d_out;

    precompute_kernel<<<2, 256>>>(constants, scales, rotations, centers);
    fused_kernel<<<TOTAL_BLK, TPB>>>(samples, grid, w2g, out);
}